// round 14
// baseline (speedup 1.0000x reference)
#include <cuda_runtime.h>

#define BB 16384
#define NSITES 784
#define OO 10
#define LABEL 392
#define LLEFT 391
#define LRIGHT 390
#define NSIDE 64
#define NTHR 256
#define EXBASE (LLEFT * 128)
#define SWF (EXBASE + 4096)

typedef unsigned long long u64;

__device__ __forceinline__ u64 pk2(float a, float b) {
    u64 r; asm("mov.b64 %0, {%1, %2};" : "=l"(r) : "f"(a), "f"(b)); return r;
}
__device__ __forceinline__ void upk2(float& a, float& b, u64 r) {
    asm("mov.b64 {%0, %1}, %2;" : "=f"(a), "=f"(b) : "l"(r));
}
__device__ __forceinline__ u64 fma2(u64 a, u64 b, u64 c) {
    u64 d; asm("fma.rn.f32x2 %0, %1, %2, %3;" : "=l"(d) : "l"(a), "l"(b), "l"(c)); return d;
}
__device__ __forceinline__ u64 mul2(u64 a, u64 b) {
    u64 d; asm("mul.rn.f32x2 %0, %1, %2;" : "=l"(d) : "l"(a), "l"(b)); return d;
}

// split-half tables: per site 128 floats = [h0: 64][h1: 64];
// half h, input slot i (permuted), jj<4 -> A out jj; jj>=4 -> C out jj-4
__device__ __align__(16) float g_WL[LLEFT * 128];
__device__ __align__(16) float g_WR[LRIGHT * 128];
__device__ __align__(8)  float g_Alab[640];
__device__ __align__(8)  float g_Clab[640];
__device__ float g_w0c[16];
__device__ float g_wlastc[16];
__device__ __align__(16) float g_vleft[BB * 8];
__device__ __align__(16) float g_u[BB * 8];
__device__ unsigned g_flag[NSIDE];

__global__ void prep_weights(const float* __restrict__ wl, const float* __restrict__ wlab,
                             const float* __restrict__ wr, const float* __restrict__ w0,
                             const float* __restrict__ wlast) {
    int idx = blockIdx.x * blockDim.x + threadIdx.x;
    if (idx < LLEFT * 128) {
        int s = idx >> 7, r = idx & 127, h = r >> 6, q = r & 63, i = q >> 3, jj = q & 7;
        int ii = (i < 4) ? h * 4 + i : (1 - h) * 4 + i - 4;
        int e = h * 4 + (jj & 3);
        float a = wl[((s * 8 + ii) * 2 + 0) * 8 + e];
        float b = wl[((s * 8 + ii) * 2 + 1) * 8 + e];
        g_WL[s * 128 + h * 64 + i * 8 + jj] = (jj >= 4) ? (b - a) : a;
        return;
    }
    idx -= LLEFT * 128;
    if (idx < LRIGHT * 128) {           // step t = site 782-t, transposed
        int t = idx >> 7, r = idx & 127, h = r >> 6, q = r & 63, i = q >> 3, jj = q & 7;
        int ii = (i < 4) ? h * 4 + i : (1 - h) * 4 + i - 4;
        int o = h * 4 + (jj & 3);
        int sl = (LRIGHT - 1) - t;
        float a = wr[((sl * 8 + o) * 2 + 0) * 8 + ii];
        float b = wr[((sl * 8 + o) * 2 + 1) * 8 + ii];
        g_WR[t * 128 + h * 64 + i * 8 + jj] = (jj >= 4) ? (b - a) : a;
        return;
    }
    idx -= LRIGHT * 128;
    if (idx < 640) {
        int o = idx % OO, de = idx / OO, e = de & 7, d = de >> 3;
        float a = wlab[(d * 16 + e) * OO + o];
        float b = wlab[(d * 16 + 8 + e) * OO + o];
        g_Alab[(d * 8 + e) * OO + o] = a;
        g_Clab[(d * 8 + e) * OO + o] = b - a;
        return;
    }
    idx -= 640;
    if (idx < 8) { g_w0c[idx] = w0[idx]; g_w0c[8 + idx] = w0[8 + idx] - w0[idx]; return; }
    idx -= 8;
    if (idx < 8) {
        g_wlastc[idx] = wlast[idx * 2];
        g_wlastc[8 + idx] = wlast[idx * 2 + 1] - wlast[idx * 2];
        return;
    }
    idx -= 8;
    if (idx < NSIDE) g_flag[idx] = 0;
}

// one site, this warp's half (4 outputs) for 2 rows; exchange via smem + named bar
__device__ __forceinline__ void half_step(const float* __restrict__ w,
        float (&v0)[8], float (&v1)[8], float p0, float p1,
        float* __restrict__ eW, const float* __restrict__ eR, int barId) {
    const ulonglong2* __restrict__ q = (const ulonglong2*)w;
    u64 A0, A1, C0, C1, B0, B1, D0, D1;
    {
        u64 x0 = pk2(v0[0], v0[0]), x1 = pk2(v1[0], v1[0]);
        ulonglong2 t = q[0], u_ = q[1];
        A0 = mul2(x0, t.x);  A1 = mul2(x0, t.y);
        C0 = mul2(x0, u_.x); C1 = mul2(x0, u_.y);
        B0 = mul2(x1, t.x);  B1 = mul2(x1, t.y);
        D0 = mul2(x1, u_.x); D1 = mul2(x1, u_.y);
    }
    #pragma unroll
    for (int i = 1; i < 8; i++) {
        u64 x0 = pk2(v0[i], v0[i]), x1 = pk2(v1[i], v1[i]);
        ulonglong2 t = q[2 * i], u_ = q[2 * i + 1];
        A0 = fma2(x0, t.x, A0);  A1 = fma2(x0, t.y, A1);
        C0 = fma2(x0, u_.x, C0); C1 = fma2(x0, u_.y, C1);
        B0 = fma2(x1, t.x, B0);  B1 = fma2(x1, t.y, B1);
        D0 = fma2(x1, u_.x, D0); D1 = fma2(x1, u_.y, D1);
    }
    u64 pp0 = pk2(p0, p0), pp1 = pk2(p1, p1);
    A0 = fma2(pp0, C0, A0); A1 = fma2(pp0, C1, A1);
    B0 = fma2(pp1, D0, B0); B1 = fma2(pp1, D1, B1);
    float a0, a1, a2, a3, b0, b1, b2, b3;
    upk2(a0, a1, A0); upk2(a2, a3, A1); upk2(b0, b1, B0); upk2(b2, b3, B1);
    *(float4*)eW         = make_float4(a0, a1, a2, a3);
    *(float4*)(eW + 128) = make_float4(b0, b1, b2, b3);
    asm volatile("bar.sync %0, 64;" :: "r"(barId) : "memory");
    float4 o0 = *(const float4*)eR;
    float4 o1 = *(const float4*)(eR + 128);
    v0[0] = a0; v0[1] = a1; v0[2] = a2; v0[3] = a3;
    v0[4] = o0.x; v0[5] = o0.y; v0[6] = o0.z; v0[7] = o0.w;
    v1[0] = b0; v1[1] = b1; v1[2] = b2; v1[3] = b3;
    v1[4] = o1.x; v1[5] = o1.y; v1[6] = o1.z; v1[7] = o1.w;
}

__device__ __forceinline__ void label_row(const u64* __restrict__ sA, const u64* __restrict__ sC,
                                          const float (&vl)[8], const float (&uu)[8],
                                          float p, float* __restrict__ out, int row) {
    const u64 p2 = pk2(p, p);
    u64 acc[5] = {0, 0, 0, 0, 0};
    #pragma unroll
    for (int d = 0; d < 8; d++) {
        #pragma unroll
        for (int e = 0; e < 8; e++) {
            const float g = vl[d] * uu[e];
            const u64 g2 = pk2(g, g);
            const u64 gp2 = mul2(g2, p2);
            const int base = (d * 8 + e) * 5;
            #pragma unroll
            for (int k = 0; k < 5; k++) {
                acc[k] = fma2(g2, sA[base + k], acc[k]);
                acc[k] = fma2(gp2, sC[base + k], acc[k]);
            }
        }
    }
    float2* o2 = (float2*)(out + row * OO);
    #pragma unroll
    for (int k = 0; k < 5; k++) { float lo, hi; upk2(lo, hi, acc[k]); o2[k] = make_float2(lo, hi); }
}

__global__ __launch_bounds__(NTHR, 1) void chain_kernel(const float* __restrict__ x,
                                                        float* __restrict__ out) {
    extern __shared__ float sw[];
    __shared__ unsigned s_old;
    const int tid = threadIdx.x, blk = blockIdx.x;
    const bool isLeft = blk < NSIDE;
    const int pairIdx = blk & (NSIDE - 1);
    const int wid = tid >> 5, lane = tid & 31;
    const int smsp = wid & 3, h = wid >> 2;
    const int barId = 1 + smsp;

    {
        const float4* g4 = (const float4*)(isLeft ? g_WL : g_WR);
        float4* s4 = (float4*)sw;
        const int n4 = (isLeft ? LLEFT : LRIGHT) * 32;
        for (int i = tid; i < n4; i += NTHR) s4[i] = g4[i];
    }
    __syncthreads();

    const int r0 = pairIdx * 256 + smsp * 64 + lane * 2;
    const int r1 = r0 + 1;
    const float* px0 = x + (size_t)r0 * NSITES;
    const float* px1 = x + (size_t)r1 * NSITES;

    float* eW = sw + EXBASE + smsp * 1024 + h * 256 + lane * 4;
    const float* eR = sw + EXBASE + smsp * 1024 + (1 - h) * 256 + lane * 4;
    int bo = 0;                         // buffer offset toggles 0 / 512

    float v0[8], v1[8];
    float st0[8], st1[8];
    if (isLeft) {
        float4 f0 = *(const float4*)px0;
        float4 f1 = *(const float4*)px1;
        #pragma unroll
        for (int d = 0; d < 8; d++) {
            st0[d] = fmaf(f0.x, g_w0c[8 + d], g_w0c[d]);
            st1[d] = fmaf(f1.x, g_w0c[8 + d], g_w0c[d]);
        }
        #pragma unroll
        for (int k = 0; k < 4; k++) {
            v0[k] = st0[h * 4 + k];     v0[4 + k] = st0[(1 - h) * 4 + k];
            v1[k] = st1[h * 4 + k];     v1[4 + k] = st1[(1 - h) * 4 + k];
        }
        float4 n0 = *(const float4*)(px0 + 4);
        float4 n1 = *(const float4*)(px1 + 4);
        const float* wp = sw + h * 64;
        half_step(wp, v0, v1, f0.y, f1.y, eW + bo, eR + bo, barId); bo ^= 512; wp += 128;
        half_step(wp, v0, v1, f0.z, f1.z, eW + bo, eR + bo, barId); bo ^= 512; wp += 128;
        half_step(wp, v0, v1, f0.w, f1.w, eW + bo, eR + bo, barId); bo ^= 512; wp += 128;
        #pragma unroll 1
        for (int g = 1; g <= 97; g++) {
            f0 = n0; f1 = n1;
            n0 = *(const float4*)(px0 + 4 * g + 4);
            n1 = *(const float4*)(px1 + 4 * g + 4);
            half_step(wp, v0, v1, f0.x, f1.x, eW + bo, eR + bo, barId); bo ^= 512; wp += 128;
            half_step(wp, v0, v1, f0.y, f1.y, eW + bo, eR + bo, barId); bo ^= 512; wp += 128;
            half_step(wp, v0, v1, f0.z, f1.z, eW + bo, eR + bo, barId); bo ^= 512; wp += 128;
            half_step(wp, v0, v1, f0.w, f1.w, eW + bo, eR + bo, barId); bo ^= 512; wp += 128;
        }
    } else {
        float4 f0 = *(const float4*)(px0 + 780);
        float4 f1 = *(const float4*)(px1 + 780);
        #pragma unroll
        for (int d = 0; d < 8; d++) {
            st0[d] = fmaf(f0.w, g_wlastc[8 + d], g_wlastc[d]);
            st1[d] = fmaf(f1.w, g_wlastc[8 + d], g_wlastc[d]);
        }
        #pragma unroll
        for (int k = 0; k < 4; k++) {
            v0[k] = st0[h * 4 + k];     v0[4 + k] = st0[(1 - h) * 4 + k];
            v1[k] = st1[h * 4 + k];     v1[4 + k] = st1[(1 - h) * 4 + k];
        }
        float4 n0 = *(const float4*)(px0 + 776);
        float4 n1 = *(const float4*)(px1 + 776);
        const float* wp = sw + h * 64;
        half_step(wp, v0, v1, f0.z, f1.z, eW + bo, eR + bo, barId); bo ^= 512; wp += 128;
        half_step(wp, v0, v1, f0.y, f1.y, eW + bo, eR + bo, barId); bo ^= 512; wp += 128;
        half_step(wp, v0, v1, f0.x, f1.x, eW + bo, eR + bo, barId); bo ^= 512; wp += 128;
        #pragma unroll 1
        for (int m = 0; m < 96; m++) {
            f0 = n0; f1 = n1;
            n0 = *(const float4*)(px0 + 772 - 4 * m);
            n1 = *(const float4*)(px1 + 772 - 4 * m);
            half_step(wp, v0, v1, f0.w, f1.w, eW + bo, eR + bo, barId); bo ^= 512; wp += 128;
            half_step(wp, v0, v1, f0.z, f1.z, eW + bo, eR + bo, barId); bo ^= 512; wp += 128;
            half_step(wp, v0, v1, f0.y, f1.y, eW + bo, eR + bo, barId); bo ^= 512; wp += 128;
            half_step(wp, v0, v1, f0.x, f1.x, eW + bo, eR + bo, barId); bo ^= 512; wp += 128;
        }
        f0 = n0; f1 = n1;                   // x[392..395]: sites 395,394,393
        half_step(wp, v0, v1, f0.w, f1.w, eW + bo, eR + bo, barId); bo ^= 512; wp += 128;
        half_step(wp, v0, v1, f0.z, f1.z, eW + bo, eR + bo, barId); bo ^= 512; wp += 128;
        half_step(wp, v0, v1, f0.y, f1.y, eW + bo, eR + bo, barId); bo ^= 512;
    }

    // h==0 holds natural-order full vectors; store side results
    if (h == 0) {
        float* base = isLeft ? g_vleft : g_u;
        float4* d0 = (float4*)(base + r0 * 8);
        d0[0] = make_float4(v0[0], v0[1], v0[2], v0[3]);
        d0[1] = make_float4(v0[4], v0[5], v0[6], v0[7]);
        float4* d1 = (float4*)(base + r1 * 8);
        d1[0] = make_float4(v1[0], v1[1], v1[2], v1[3]);
        d1[1] = make_float4(v1[4], v1[5], v1[6], v1[7]);
    }

    __threadfence();
    __syncthreads();
    if (tid == 0) s_old = atomicAdd(&g_flag[pairIdx], 1u);
    __syncthreads();
    if (!(s_old & 1)) return;               // first arriver exits
    __threadfence();
    if (h == 1) return;                     // tids 0..127 remain

    for (int i = tid; i < 320; i += 128) {
        ((u64*)sw)[i]       = ((const u64*)g_Alab)[i];
        ((u64*)sw)[320 + i] = ((const u64*)g_Clab)[i];
    }
    asm volatile("bar.sync 5, 128;" ::: "memory");
    const u64* sA = (const u64*)sw;
    const u64* sC = sA + 320;

    const float* other = isLeft ? g_u : g_vleft;
    #pragma unroll 1
    for (int rr = 0; rr < 2; rr++) {
        const int row = rr == 0 ? r0 : r1;
        float vv[8], oo[8];
        #pragma unroll
        for (int e = 0; e < 8; e++) vv[e] = (rr == 0) ? v0[e] : v1[e];
        const float4* s0 = (const float4*)(other + row * 8);
        float4 a = s0[0], b = s0[1];
        oo[0] = a.x; oo[1] = a.y; oo[2] = a.z; oo[3] = a.w;
        oo[4] = b.x; oo[5] = b.y; oo[6] = b.z; oo[7] = b.w;
        const float pl = x[(size_t)row * NSITES + LABEL];
        if (isLeft) label_row(sA, sC, vv, oo, pl, out, row);
        else        label_row(sA, sC, oo, vv, pl, out, row);
    }
}

extern "C" void kernel_launch(void* const* d_in, const int* in_sizes, int n_in,
                              void* d_out, int out_size) {
    const float* x      = (const float*)d_in[0];
    const float* w0     = (const float*)d_in[1];
    const float* Wleft  = (const float*)d_in[2];
    const float* wlabel = (const float*)d_in[3];
    const float* Wright = (const float*)d_in[4];
    const float* wlast  = (const float*)d_in[5];
    float* out = (float*)d_out;

    const int smemBytes = SWF * (int)sizeof(float);   // 216,576 B
    cudaFuncSetAttribute(chain_kernel, cudaFuncAttributeMaxDynamicSharedMemorySize, smemBytes);

    const int prepN = LLEFT * 128 + LRIGHT * 128 + 640 + 8 + 8 + NSIDE;
    prep_weights<<<(prepN + 255) / 256, 256>>>(Wleft, wlabel, Wright, w0, wlast);
    chain_kernel<<<2 * NSIDE, NTHR, smemBytes>>>(x, out);
}